// round 5
// baseline (speedup 1.0000x reference)
#include <cuda_runtime.h>
#include <cstdint>

// Problem constants (fixed shapes from reference)
#define VDIM 32000      // vocab
#define KD   64         // per-group feature dim
#define GG   8          // group elements
#define KK   512        // GG*KD  (GEMM reduction dim)
#define MM   2048       // B*N    (GEMM M dim)

// ---------------- scratch (static device globals; no allocs) ----------------
__device__ __align__(16) float g_Bg[(size_t)KK * VDIM];   // gathered B: [KK][VDIM], 65.5 MB
__device__ float g_rowmax[MM];
__device__ float g_rowsum[MM];
__device__ int   g_perm_is64;

// ---------------- kernel 0: detect perm dtype (int64 vs int32) ----------------
// If the buffer really holds int64 indices, every 8-byte word is in [0, VDIM).
// If it holds int32, an int64 read fuses two entries -> high word nonzero with
// probability ~(1 - 1/32000) per entry; 256 entries misclassify with prob ~0.
__global__ void detect_perm_kernel(const void* __restrict__ perm) {
    const long long* p64 = (const long long*)perm;
    int ok = 1;
    for (int i = 0; i < 256; i++) {
        long long v = p64[i];
        if (v < 0 || v >= VDIM) { ok = 0; break; }
    }
    g_perm_is64 = ok;
}

// ---------------- kernel 1: gather psi rows via perm ----------------
// Bg[(h*64+k)][v] = psi[perm[h][v]*64 + k]
__global__ void gather_kernel(const float* __restrict__ psi,
                              const void* __restrict__ perm) {
    int v = blockIdx.x * blockDim.x + threadIdx.x;
    int h = blockIdx.y;
    if (v >= VDIM) return;
    size_t idx = (size_t)h * VDIM + v;
    long long p;
    if (g_perm_is64) {
        p = ((const long long*)perm)[idx];
    } else {
        p = (long long)((const int*)perm)[idx];
    }
    // defensive clamp (wrong perm dtype would give garbage, not a crash)
    if (p < 0) p = 0;
    if (p >= VDIM) p = VDIM - 1;
    const float* src = psi + (size_t)p * KD;
    float* dst = g_Bg + (size_t)h * KD * VDIM + v;
#pragma unroll
    for (int k = 0; k < KD; k++) {
        dst[(size_t)k * VDIM] = __ldg(src + k);
    }
}

// ---------------- kernel 2: SGEMM 2048 x 32000 x 512 ----------------
// C[m][v] = sum_k A[m][k] * Bg[k][v].  BM=BN=128, BK=8, 256 threads, 8x8 microtile.
#define BM 128
#define BN 128
#define BK 8
#define TM 8
#define TN 8

__global__ void __launch_bounds__(256) gemm_kernel(const float* __restrict__ A,
                                                   float* __restrict__ C) {
    __shared__ float As[BK][BM];
    __shared__ float Bs[BK][BN];

    const int tid = threadIdx.x;
    const int tx = tid & 15;          // 0..15  (v direction)
    const int ty = tid >> 4;          // 0..15  (m direction)
    const int m0 = blockIdx.y * BM;
    const int v0 = blockIdx.x * BN;

    // A-tile loader: 128 rows x 8 k; each thread loads one float4 along k
    const int a_row = tid >> 1;            // 0..127
    const int a_col = (tid & 1) * 4;       // 0 or 4
    // B-tile loader: 8 rows x 128 v; each thread loads one float4 along v
    const int b_row = tid >> 5;            // 0..7
    const int b_col = (tid & 31) * 4;      // 0..124

    const float* Aptr = A + (size_t)m0 * KK;

    float acc[TM][TN];
#pragma unroll
    for (int i = 0; i < TM; i++)
#pragma unroll
        for (int j = 0; j < TN; j++) acc[i][j] = 0.0f;

    for (int k0 = 0; k0 < KK; k0 += BK) {
        float4 a4 = *reinterpret_cast<const float4*>(Aptr + (size_t)a_row * KK + k0 + a_col);
        As[a_col + 0][a_row] = a4.x;
        As[a_col + 1][a_row] = a4.y;
        As[a_col + 2][a_row] = a4.z;
        As[a_col + 3][a_row] = a4.w;

        float4 b4 = *reinterpret_cast<const float4*>(
            g_Bg + (size_t)(k0 + b_row) * VDIM + v0 + b_col);
        *reinterpret_cast<float4*>(&Bs[b_row][b_col]) = b4;

        __syncthreads();

#pragma unroll
        for (int kk = 0; kk < BK; kk++) {
            float rA[TM], rB[TN];
#pragma unroll
            for (int i = 0; i < TM; i++) rA[i] = As[kk][ty * TM + i];
#pragma unroll
            for (int j = 0; j < TN; j++) rB[j] = Bs[kk][tx * TN + j];
#pragma unroll
            for (int i = 0; i < TM; i++)
#pragma unroll
                for (int j = 0; j < TN; j++)
                    acc[i][j] = fmaf(rA[i], rB[j], acc[i][j]);
        }
        __syncthreads();
    }

#pragma unroll
    for (int i = 0; i < TM; i++) {
        float* crow = C + (size_t)(m0 + ty * TM + i) * VDIM + v0 + tx * TN;
#pragma unroll
        for (int j = 0; j < TN; j += 4) {
            float4 c4 = make_float4(acc[i][j], acc[i][j + 1], acc[i][j + 2], acc[i][j + 3]);
            *reinterpret_cast<float4*>(crow + j) = c4;
        }
    }
}

// ---------------- kernel 3: per-row online max + sum(exp) ----------------
__global__ void rowstat_kernel(const float* __restrict__ C) {
    const int row = blockIdx.x;
    const float4* x = reinterpret_cast<const float4*>(C + (size_t)row * VDIM);

    float m = -3.4e38f, s = 0.0f;
    for (int i = threadIdx.x; i < VDIM / 4; i += blockDim.x) {
        float4 v4 = x[i];
        float vals[4] = {v4.x, v4.y, v4.z, v4.w};
#pragma unroll
        for (int j = 0; j < 4; j++) {
            float val = vals[j];
            float nm = fmaxf(m, val);
            s = s * __expf(m - nm) + __expf(val - nm);
            m = nm;
        }
    }
    // warp reduce
#pragma unroll
    for (int off = 16; off; off >>= 1) {
        float om = __shfl_xor_sync(0xFFFFFFFFu, m, off);
        float os = __shfl_xor_sync(0xFFFFFFFFu, s, off);
        float nm = fmaxf(m, om);
        s = s * __expf(m - nm) + os * __expf(om - nm);
        m = nm;
    }
    __shared__ float sm[8], ss[8];
    const int wid = threadIdx.x >> 5, lid = threadIdx.x & 31;
    if (lid == 0) { sm[wid] = m; ss[wid] = s; }
    __syncthreads();
    if (threadIdx.x == 0) {
        float M0 = sm[0], S0 = ss[0];
        for (int w = 1; w < 8; w++) {
            float nm = fmaxf(M0, sm[w]);
            S0 = S0 * __expf(M0 - nm) + ss[w] * __expf(sm[w] - nm);
            M0 = nm;
        }
        g_rowmax[row] = M0;
        g_rowsum[row] = S0;
    }
}

// ---------------- kernel 4: normalize in place ----------------
__global__ void norm_kernel(float* __restrict__ C) {
    size_t idx = (size_t)blockIdx.x * blockDim.x + threadIdx.x;
    const size_t total = (size_t)MM * (VDIM / 4);
    if (idx >= total) return;
    int row = (int)(idx / (VDIM / 4));
    float mm = g_rowmax[row];
    float inv = 1.0f / g_rowsum[row];
    float4* p = reinterpret_cast<float4*>(C) + idx;
    float4 v = *p;
    v.x = __expf(v.x - mm) * inv;
    v.y = __expf(v.y - mm) * inv;
    v.z = __expf(v.z - mm) * inv;
    v.w = __expf(v.w - mm) * inv;
    *p = v;
}

// ---------------- launch ----------------
extern "C" void kernel_launch(void* const* d_in, const int* in_sizes, int n_in,
                              void* d_out, int out_size) {
    const float* phi  = (const float*)d_in[0];      // [4,512,8,64] = [2048,512]
    const float* psi  = (const float*)d_in[1];      // [32000,64]
    const void*  perm = d_in[2];                    // [8,32000], int32 or int64
    float* out = (float*)d_out;                     // [2048,32000]

    detect_perm_kernel<<<1, 1>>>(perm);
    gather_kernel<<<dim3((VDIM + 255) / 256, GG), 256>>>(psi, perm);
    gemm_kernel<<<dim3(VDIM / BN, MM / BM), 256>>>(phi, out);
    rowstat_kernel<<<MM, 256>>>(out);
    {
        size_t total = (size_t)MM * (VDIM / 4);
        int blocks = (int)((total + 255) / 256);
        norm_kernel<<<blocks, 256>>>(out);
    }
}

// round 7
// speedup vs baseline: 1.0005x; 1.0005x over previous
#include <cuda_runtime.h>
#include <cstdint>

// Problem constants (fixed shapes from reference)
#define VDIM 32000      // vocab
#define KD   64         // per-group feature dim
#define GG   8          // group elements
#define KK   512        // GG*KD  (GEMM reduction dim)
#define MM   2048       // B*N    (GEMM M dim)

// ---------------- scratch (static device globals; no allocs) ----------------
__device__ __align__(16) float g_Bg[(size_t)KK * VDIM];   // gathered B: [KK][VDIM], 65.5 MB
__device__ float g_rowmax[MM];
__device__ float g_rowsum[MM];
__device__ int   g_perm_is64;

// ---------------- kernel 0: detect perm dtype (int64 vs int32) ----------------
// If the buffer really holds int64 indices, every 8-byte word is in [0, VDIM).
// If it holds int32, an int64 read fuses two entries -> high word nonzero with
// probability ~(1 - 1/32000) per entry; 256 entries misclassify with prob ~0.
__global__ void detect_perm_kernel(const void* __restrict__ perm) {
    const long long* p64 = (const long long*)perm;
    int ok = 1;
    for (int i = 0; i < 256; i++) {
        long long v = p64[i];
        if (v < 0 || v >= VDIM) { ok = 0; break; }
    }
    g_perm_is64 = ok;
}

// ---------------- kernel 1: gather psi rows via perm ----------------
// Bg[(h*64+k)][v] = psi[perm[h][v]*64 + k]
__global__ void gather_kernel(const float* __restrict__ psi,
                              const void* __restrict__ perm) {
    int v = blockIdx.x * blockDim.x + threadIdx.x;
    int h = blockIdx.y;
    if (v >= VDIM) return;
    size_t idx = (size_t)h * VDIM + v;
    long long p;
    if (g_perm_is64) {
        p = ((const long long*)perm)[idx];
    } else {
        p = (long long)((const int*)perm)[idx];
    }
    // defensive clamp (wrong perm dtype would give garbage, not a crash)
    if (p < 0) p = 0;
    if (p >= VDIM) p = VDIM - 1;
    const float* src = psi + (size_t)p * KD;
    float* dst = g_Bg + (size_t)h * KD * VDIM + v;
#pragma unroll
    for (int k = 0; k < KD; k++) {
        dst[(size_t)k * VDIM] = __ldg(src + k);
    }
}

// ---------------- kernel 2: SGEMM 2048 x 32000 x 512 ----------------
// C[m][v] = sum_k A[m][k] * Bg[k][v].  BM=BN=128, BK=8, 256 threads, 8x8 microtile.
#define BM 128
#define BN 128
#define BK 8
#define TM 8
#define TN 8

__global__ void __launch_bounds__(256) gemm_kernel(const float* __restrict__ A,
                                                   float* __restrict__ C) {
    __shared__ float As[BK][BM];
    __shared__ float Bs[BK][BN];

    const int tid = threadIdx.x;
    const int tx = tid & 15;          // 0..15  (v direction)
    const int ty = tid >> 4;          // 0..15  (m direction)
    const int m0 = blockIdx.y * BM;
    const int v0 = blockIdx.x * BN;

    // A-tile loader: 128 rows x 8 k; each thread loads one float4 along k
    const int a_row = tid >> 1;            // 0..127
    const int a_col = (tid & 1) * 4;       // 0 or 4
    // B-tile loader: 8 rows x 128 v; each thread loads one float4 along v
    const int b_row = tid >> 5;            // 0..7
    const int b_col = (tid & 31) * 4;      // 0..124

    const float* Aptr = A + (size_t)m0 * KK;

    float acc[TM][TN];
#pragma unroll
    for (int i = 0; i < TM; i++)
#pragma unroll
        for (int j = 0; j < TN; j++) acc[i][j] = 0.0f;

    for (int k0 = 0; k0 < KK; k0 += BK) {
        float4 a4 = *reinterpret_cast<const float4*>(Aptr + (size_t)a_row * KK + k0 + a_col);
        As[a_col + 0][a_row] = a4.x;
        As[a_col + 1][a_row] = a4.y;
        As[a_col + 2][a_row] = a4.z;
        As[a_col + 3][a_row] = a4.w;

        float4 b4 = *reinterpret_cast<const float4*>(
            g_Bg + (size_t)(k0 + b_row) * VDIM + v0 + b_col);
        *reinterpret_cast<float4*>(&Bs[b_row][b_col]) = b4;

        __syncthreads();

#pragma unroll
        for (int kk = 0; kk < BK; kk++) {
            float rA[TM], rB[TN];
#pragma unroll
            for (int i = 0; i < TM; i++) rA[i] = As[kk][ty * TM + i];
#pragma unroll
            for (int j = 0; j < TN; j++) rB[j] = Bs[kk][tx * TN + j];
#pragma unroll
            for (int i = 0; i < TM; i++)
#pragma unroll
                for (int j = 0; j < TN; j++)
                    acc[i][j] = fmaf(rA[i], rB[j], acc[i][j]);
        }
        __syncthreads();
    }

#pragma unroll
    for (int i = 0; i < TM; i++) {
        float* crow = C + (size_t)(m0 + ty * TM + i) * VDIM + v0 + tx * TN;
#pragma unroll
        for (int j = 0; j < TN; j += 4) {
            float4 c4 = make_float4(acc[i][j], acc[i][j + 1], acc[i][j + 2], acc[i][j + 3]);
            *reinterpret_cast<float4*>(crow + j) = c4;
        }
    }
}

// ---------------- kernel 3: per-row online max + sum(exp) ----------------
__global__ void rowstat_kernel(const float* __restrict__ C) {
    const int row = blockIdx.x;
    const float4* x = reinterpret_cast<const float4*>(C + (size_t)row * VDIM);

    float m = -3.4e38f, s = 0.0f;
    for (int i = threadIdx.x; i < VDIM / 4; i += blockDim.x) {
        float4 v4 = x[i];
        float vals[4] = {v4.x, v4.y, v4.z, v4.w};
#pragma unroll
        for (int j = 0; j < 4; j++) {
            float val = vals[j];
            float nm = fmaxf(m, val);
            s = s * __expf(m - nm) + __expf(val - nm);
            m = nm;
        }
    }
    // warp reduce
#pragma unroll
    for (int off = 16; off; off >>= 1) {
        float om = __shfl_xor_sync(0xFFFFFFFFu, m, off);
        float os = __shfl_xor_sync(0xFFFFFFFFu, s, off);
        float nm = fmaxf(m, om);
        s = s * __expf(m - nm) + os * __expf(om - nm);
        m = nm;
    }
    __shared__ float sm[8], ss[8];
    const int wid = threadIdx.x >> 5, lid = threadIdx.x & 31;
    if (lid == 0) { sm[wid] = m; ss[wid] = s; }
    __syncthreads();
    if (threadIdx.x == 0) {
        float M0 = sm[0], S0 = ss[0];
        for (int w = 1; w < 8; w++) {
            float nm = fmaxf(M0, sm[w]);
            S0 = S0 * __expf(M0 - nm) + ss[w] * __expf(sm[w] - nm);
            M0 = nm;
        }
        g_rowmax[row] = M0;
        g_rowsum[row] = S0;
    }
}

// ---------------- kernel 4: normalize in place ----------------
__global__ void norm_kernel(float* __restrict__ C) {
    size_t idx = (size_t)blockIdx.x * blockDim.x + threadIdx.x;
    const size_t total = (size_t)MM * (VDIM / 4);
    if (idx >= total) return;
    int row = (int)(idx / (VDIM / 4));
    float mm = g_rowmax[row];
    float inv = 1.0f / g_rowsum[row];
    float4* p = reinterpret_cast<float4*>(C) + idx;
    float4 v = *p;
    v.x = __expf(v.x - mm) * inv;
    v.y = __expf(v.y - mm) * inv;
    v.z = __expf(v.z - mm) * inv;
    v.w = __expf(v.w - mm) * inv;
    *p = v;
}

// ---------------- launch ----------------
extern "C" void kernel_launch(void* const* d_in, const int* in_sizes, int n_in,
                              void* d_out, int out_size) {
    const float* phi  = (const float*)d_in[0];      // [4,512,8,64] = [2048,512]
    const float* psi  = (const float*)d_in[1];      // [32000,64]
    const void*  perm = d_in[2];                    // [8,32000], int32 or int64
    float* out = (float*)d_out;                     // [2048,32000]

    detect_perm_kernel<<<1, 1>>>(perm);
    gather_kernel<<<dim3((VDIM + 255) / 256, GG), 256>>>(psi, perm);
    gemm_kernel<<<dim3(VDIM / BN, MM / BM), 256>>>(phi, out);
    rowstat_kernel<<<MM, 256>>>(out);
    {
        size_t total = (size_t)MM * (VDIM / 4);
        int blocks = (int)((total + 255) / 256);
        norm_kernel<<<blocks, 256>>>(out);
    }
}